// round 3
// baseline (speedup 1.0000x reference)
#include <cuda_runtime.h>

#define N_ 4
#define CI_ 64
#define CO_ 64
#define L_ 1024
#define V_ 25
#define P_ 3
#define VP_ 32      // padded V for power-of-2 tiling
#define KW_ 9       // temporal window
#define LT_ 4       // l-values per block in main kernel
#define WROW_ 68    // padded row stride (floats) for W and Y tiles in smem

// ---------------- scratch (__device__ globals; no allocations) ----------------
__device__ float g_xs[N_*L_*CI_*VP_];    // [n][l][ci][32] temporally pre-summed x
__device__ float g_u [N_*CO_*L_*V_];     // [n][c][l][w] pre-BN activations (final layout)
__device__ float g_Wt[P_*CI_*CO_];       // [p][ci][c]
__device__ float g_Ae[P_*V_*VP_];        // [p][v][32] (A*edge, zero-padded)
__device__ float g_beff[CO_*VP_];        // [c][32]  sum_p b[p,c]*colsumA[p,w]
__device__ float g_sum[CO_];
__device__ float g_sumsq[CO_];
__device__ float g_scale[CO_];
__device__ float g_shift[CO_];

// ---------------- k0: weight folding + stat zeroing ----------------
__global__ void k0_prep(const float* __restrict__ A, const float* __restrict__ edge,
                        const float* __restrict__ cw, const float* __restrict__ cb) {
    int tid = threadIdx.x;
    // A*edge, padded to 32 in w
    for (int i = tid; i < P_*V_*VP_; i += blockDim.x) {
        int p = i / (V_*VP_); int r = i % (V_*VP_); int v = r / VP_; int w = r % VP_;
        float val = 0.f;
        if (w < V_) { int j = (p*V_+v)*V_+w; val = A[j]*edge[j]; }
        g_Ae[i] = val;
    }
    // bias_eff[c][w] = sum_p b[p,c] * sum_v Ae[p,v,w]
    for (int i = tid; i < CO_*VP_; i += blockDim.x) {
        int c = i / VP_; int w = i % VP_;
        float s = 0.f;
        if (w < V_) {
            for (int p = 0; p < P_; p++) {
                float col = 0.f;
                for (int v = 0; v < V_; v++) { int j = (p*V_+v)*V_+w; col += A[j]*edge[j]; }
                s += cb[p*CO_+c]*col;
            }
        }
        g_beff[i] = s;
    }
    // W transposed: g_Wt[(p*CI+ci)*CO + c] = conv_w[(p*CO+c)*CI + ci]
    for (int i = tid; i < P_*CI_*CO_; i += blockDim.x) {
        int p = i / (CI_*CO_); int r = i % (CI_*CO_); int ci = r / CO_; int c = r % CO_;
        g_Wt[i] = cw[(p*CO_+c)*CI_ + ci];
    }
    if (tid < CO_) { g_sum[tid] = 0.f; g_sumsq[tid] = 0.f; }
}

// ---------------- k1: temporal sliding sum (window [l-8, l]) + transpose + pad ----
// FIX (R2): preload from l0-KW_ (9 elems) so the drop at l=l0 removes an element
// that is actually in the accumulator. Previous version preloaded only 8 and the
// first drop corrupted the running sum for the whole chunk.
#define CHUNK_ 128
__global__ void k1_presum(const float* __restrict__ x) {
    int gtid = blockIdx.x*blockDim.x + threadIdx.x;
    int warp = gtid >> 5;
    int v    = gtid & 31;
    if (warp >= N_*CI_*(L_/CHUNK_)) return;
    int n     = warp / (CI_*(L_/CHUNK_));
    int rem   = warp % (CI_*(L_/CHUNK_));
    int ci    = rem / (L_/CHUNK_);
    int chunk = rem % (L_/CHUNK_);
    int l0 = chunk*CHUNK_;
    int obase = (n*L_*CI_ + ci)*VP_ + v;         // + l*CI_*VP_
    if (v >= V_) {
        for (int l = l0; l < l0+CHUNK_; l++) g_xs[obase + l*CI_*VP_] = 0.f;
        return;
    }
    const float* xb = x + (n*CI_+ci)*L_*V_ + v;  // + l*V_
    float s = 0.f;
    int jstart = l0 - KW_; if (jstart < 0) jstart = 0;
    for (int j = jstart; j < l0; j++) s += xb[j*V_];
    for (int l = l0; l < l0+CHUNK_; l++) {
        s += xb[l*V_];
        int ldrop = l - KW_;
        if (ldrop >= 0) s -= xb[ldrop*V_];
        g_xs[obase + l*CI_*VP_] = s;
    }
}

// ---------------- k2: fused conv GEMM + graph GEMM + bias + stats ----------------
// smem float offsets
#define SW_OFF 0                       // 3*64*68 = 13056
#define SA_OFF 13056                   // 3*25*32 = 2400
#define SB_OFF 15456                   // 64*32   = 2048
#define SX_OFF 17504                   // 4*64*32 = 8192
#define SY_OFF 25696                   // 32*68   = 2176
#define SS_OFF 27872                   // 128
#define SMEM_FLOATS 28000              // 112000 bytes

__global__ void k2_main() {
    extern __shared__ float sm[];
    int tid = threadIdx.x;             // 128 threads
    int n   = blockIdx.y;
    int l0  = blockIdx.x * LT_;

    // load W (coalesced read, strided smem write — row stride 68 keeps conflicts low)
    for (int i = tid; i < P_*CI_*CO_; i += 128) {
        int row = i >> 6; int c = i & 63;
        sm[SW_OFF + row*WROW_ + c] = g_Wt[i];
    }
    for (int i = tid; i < P_*V_*VP_; i += 128) sm[SA_OFF + i] = g_Ae[i];
    for (int i = tid; i < CO_*VP_;  i += 128) sm[SB_OFF + i] = g_beff[i];
    {
        const float4* src = (const float4*)(g_xs + (n*L_ + l0)*CI_*VP_);
        float4* dst = (float4*)(sm + SX_OFF);
        for (int i = tid; i < LT_*CI_*VP_/4; i += 128) dst[i] = src[i];
    }
    if (tid < CO_) { sm[SS_OFF + tid] = 0.f; sm[SS_OFF + 64 + tid] = 0.f; }
    __syncthreads();

    int cg = tid >> 3, vg = tid & 7;
    int c0 = cg*4, v0 = vg*4;          // v0 doubles as w0 in stage B
    float csum[4]  = {0.f,0.f,0.f,0.f};
    float csum2[4] = {0.f,0.f,0.f,0.f};

    for (int lt = 0; lt < LT_; lt++) {
        int l = l0 + lt;
        float z[4][4];
        #pragma unroll
        for (int a = 0; a < 4; a++)
            #pragma unroll
            for (int b = 0; b < 4; b++) z[a][b] = 0.f;

        for (int p = 0; p < P_; p++) {
            // ---- stage A: y1[v][c] = sum_ci xs[ci][v] * W[p][ci][c] ----
            float acc[4][4];
            #pragma unroll
            for (int a = 0; a < 4; a++)
                #pragma unroll
                for (int b = 0; b < 4; b++) acc[a][b] = 0.f;
            const float* wp = sm + SW_OFF + p*CI_*WROW_;
            const float* xp = sm + SX_OFF + lt*CI_*VP_;
            #pragma unroll 8
            for (int ci = 0; ci < CI_; ci++) {
                float4 wv = *(const float4*)(wp + ci*WROW_ + c0);
                float4 xv = *(const float4*)(xp + ci*VP_   + v0);
                float wr[4] = {wv.x, wv.y, wv.z, wv.w};
                float xr[4] = {xv.x, xv.y, xv.z, xv.w};
                #pragma unroll
                for (int vi = 0; vi < 4; vi++)
                    #pragma unroll
                    for (int cj = 0; cj < 4; cj++)
                        acc[vi][cj] += xr[vi] * wr[cj];
            }
            #pragma unroll
            for (int vi = 0; vi < 4; vi++)
                *(float4*)(sm + SY_OFF + (v0+vi)*WROW_ + c0) =
                    make_float4(acc[vi][0], acc[vi][1], acc[vi][2], acc[vi][3]);
            __syncthreads();

            // ---- stage B: z[c][w] += sum_v y1[v][c] * Ae[p][v][w] ----
            const float* ap = sm + SA_OFF + p*V_*VP_;
            #pragma unroll 5
            for (int v = 0; v < V_; v++) {
                float4 yv = *(const float4*)(sm + SY_OFF + v*WROW_ + c0);
                float4 av = *(const float4*)(ap + v*VP_ + v0);
                float yr[4] = {yv.x, yv.y, yv.z, yv.w};
                float ar[4] = {av.x, av.y, av.z, av.w};
                #pragma unroll
                for (int cj = 0; cj < 4; cj++)
                    #pragma unroll
                    for (int wi = 0; wi < 4; wi++)
                        z[cj][wi] += yr[cj] * ar[wi];
            }
            __syncthreads();
        }

        float cnt = (float)((l+1 < KW_) ? (l+1) : KW_);   // Toeplitz boundary count
        #pragma unroll
        for (int cj = 0; cj < 4; cj++) {
            float4 bv = *(const float4*)(sm + SB_OFF + (c0+cj)*VP_ + v0);
            float br[4] = {bv.x, bv.y, bv.z, bv.w};
            #pragma unroll
            for (int wi = 0; wi < 4; wi++) {
                int w = v0 + wi;
                if (w < V_) {
                    float val = z[cj][wi] + br[wi]*cnt;
                    csum[cj]  += val;
                    csum2[cj] += val*val;
                    g_u[((n*CO_ + c0+cj)*L_ + l)*V_ + w] = val;
                }
            }
        }
    }

    // block-level stat reduction, then one global atomic per channel per block
    #pragma unroll
    for (int cj = 0; cj < 4; cj++) {
        atomicAdd(&sm[SS_OFF + c0+cj],      csum[cj]);
        atomicAdd(&sm[SS_OFF + 64 + c0+cj], csum2[cj]);
    }
    __syncthreads();
    if (tid < CO_) {
        atomicAdd(&g_sum[tid],   sm[SS_OFF + tid]);
        atomicAdd(&g_sumsq[tid], sm[SS_OFF + 64 + tid]);
    }
}

// ---------------- k3: finalize BN stats ----------------
__global__ void k3_stats(const float* __restrict__ gamma, const float* __restrict__ beta) {
    int c = threadIdx.x;
    if (c < CO_) {
        const float cnt = (float)(N_*L_*V_);
        float mean = g_sum[c] / cnt;
        float var  = g_sumsq[c] / cnt - mean*mean;
        float inv  = rsqrtf(var + 1e-5f);
        float sc   = gamma[c]*inv;
        g_scale[c] = sc;
        g_shift[c] = beta[c] - mean*sc;
    }
}

// ---------------- k4: BN apply + relu + residual + relu (float4, coalesced) --------
__global__ void k4_out(const float* __restrict__ x, float* __restrict__ out) {
    int i = blockIdx.x*blockDim.x + threadIdx.x;           // float4 index
    if (i >= N_*CO_*L_*V_/4) return;
    int c = ((i*4) / (L_*V_)) % CO_;                       // L_*V_ = 25600, mult of 4
    float sc = g_scale[c], sh = g_shift[c];
    float4 u  = ((const float4*)g_u)[i];
    float4 xv = ((const float4*)x)[i];
    float4 o;
    o.x = fmaxf(fmaxf(u.x*sc + sh, 0.f) + xv.x, 0.f);
    o.y = fmaxf(fmaxf(u.y*sc + sh, 0.f) + xv.y, 0.f);
    o.z = fmaxf(fmaxf(u.z*sc + sh, 0.f) + xv.z, 0.f);
    o.w = fmaxf(fmaxf(u.w*sc + sh, 0.f) + xv.w, 0.f);
    ((float4*)out)[i] = o;
}

// ---------------- launch ----------------
extern "C" void kernel_launch(void* const* d_in, const int* in_sizes, int n_in,
                              void* d_out, int out_size) {
    const float* x     = (const float*)d_in[0];
    const float* A     = (const float*)d_in[1];
    const float* edge  = (const float*)d_in[2];
    const float* cw    = (const float*)d_in[3];
    const float* cb    = (const float*)d_in[4];
    const float* gamma = (const float*)d_in[5];
    const float* beta  = (const float*)d_in[6];
    float* out = (float*)d_out;

    cudaFuncSetAttribute(k2_main, cudaFuncAttributeMaxDynamicSharedMemorySize,
                         SMEM_FLOATS*4);

    k0_prep<<<1, 256>>>(A, edge, cw, cb);
    k1_presum<<<(N_*CI_*(L_/CHUNK_)*32 + 255)/256, 256>>>(x);
    k2_main<<<dim3(L_/LT_, N_), 128, SMEM_FLOATS*4>>>();
    k3_stats<<<1, 64>>>(gamma, beta);
    k4_out<<<(N_*CO_*L_*V_/4 + 255)/256, 256>>>(x, out);
}

// round 5
// speedup vs baseline: 1.3048x; 1.3048x over previous
#include <cuda_runtime.h>
#include <mma.h>
#include <cstdint>

using namespace nvcuda;

#define N_ 4
#define CI_ 64
#define CO_ 64
#define L_ 1024
#define V_ 25
#define P_ 3
#define VP_ 32
#define KW_ 9
#define K2_ 192      // p*ci contraction dim
#define LT_ 8        // l-values per block in fused kernel

// ---------------- scratch (__device__ globals) ----------------
__device__ float g_xs[N_*L_*CI_*VP_];      // [n][l][ci][32v]  sliding-window presum
__device__ float g_u2[N_*L_*VP_*CO_];      // [n][l][w(32)][c] pre-BN activations
__device__ float g_W2[CO_*K2_];            // [c][192k]  k = p*64+ci
__device__ float g_Ae[P_*VP_*VP_];         // [p][v(32)][w(32)] zero-padded
__device__ float g_beff[CO_*VP_];          // [c][32w]
__device__ float g_sum[CO_], g_sumsq[CO_], g_scale[CO_], g_shift[CO_];

// ---------------- k0: fold weights ----------------
__global__ void k0_prep(const float* __restrict__ A, const float* __restrict__ edge,
                        const float* __restrict__ cw, const float* __restrict__ cb) {
    int tid = threadIdx.x + blockIdx.x * blockDim.x;
    int nth = blockDim.x * gridDim.x;
    for (int i = tid; i < CO_*K2_; i += nth) {
        int c = i / K2_, k = i % K2_, p = k >> 6, ci = k & 63;
        g_W2[i] = cw[(p*CO_ + c)*CI_ + ci];
    }
    for (int i = tid; i < P_*VP_*VP_; i += nth) {
        int p = i / (VP_*VP_), rr = i % (VP_*VP_), v = rr >> 5, w = rr & 31;
        float val = 0.f;
        if (v < V_ && w < V_) { int j = (p*V_ + v)*V_ + w; val = A[j]*edge[j]; }
        g_Ae[i] = val;
    }
    for (int i = tid; i < CO_*VP_; i += nth) {
        int c = i / VP_, w = i % VP_;
        float s = 0.f;
        if (w < V_)
            for (int p = 0; p < P_; p++) {
                float col = 0.f;
                for (int v = 0; v < V_; v++) { int j = (p*V_+v)*V_+w; col += A[j]*edge[j]; }
                s += cb[p*CO_ + c]*col;
            }
        g_beff[i] = s;
    }
    if (tid < CO_) { g_sum[tid] = 0.f; g_sumsq[tid] = 0.f; }
}

// ---------------- k1: temporal sliding sum -> g_xs [n][l][ci][32] ----------------
#define CHUNK_ 128
__global__ void k1_presum(const float* __restrict__ x) {
    int gtid = blockIdx.x*blockDim.x + threadIdx.x;
    int warp = gtid >> 5, v = gtid & 31;
    if (warp >= N_*CI_*(L_/CHUNK_)) return;
    int n = warp / (CI_*(L_/CHUNK_));
    int rem = warp % (CI_*(L_/CHUNK_));
    int ci = rem / (L_/CHUNK_), chunk = rem % (L_/CHUNK_);
    int l0 = chunk*CHUNK_;
    int obase = (n*L_*CI_ + ci)*VP_ + v;
    if (v >= V_) {
        for (int l = l0; l < l0+CHUNK_; l++) g_xs[obase + l*CI_*VP_] = 0.f;
        return;
    }
    const float* xb = x + (n*CI_+ci)*L_*V_ + v;
    float s = 0.f;
    int js = l0 - KW_; if (js < 0) js = 0;
    for (int j = js; j < l0; j++) s += xb[j*V_];
    for (int l = l0; l < l0+CHUNK_; l++) {
        s += xb[l*V_];
        int ld = l - KW_;
        if (ld >= 0) s -= xb[ld*V_];
        g_xs[obase + l*CI_*VP_] = s;
    }
}

// ---------------- k2: fused double-GEMM via wmma tf32 ----------------
// smem float offsets (all lds chosen ≡4 mod 32 for conflict-free fragment access)
#define SM_XS 0                         // [8l*64ci][ld 36]      18432
#define SM_W2 18432                     // [64c][ld 196]         12544
#define SM_AE 30976                     // [3p*32v][ld 36]        3456
#define SM_T  34432                     // [192k][ld 36]          6912
#define SM_U  41344                     // [32w][ld 68] (col c)   2176
#define SM_BF 43520                     // [32w][64c]             2048
#define SM_ST 45568                     // stats 128
#define SM_FLOATS 45696                 // 182784 bytes

__global__ void __launch_bounds__(256, 1) k2_fused() {
    extern __shared__ float sm[];
    int tid = threadIdx.x, ww = tid >> 5;
    int n = blockIdx.y, l0 = blockIdx.x * LT_;

    // ---- load all operands ----
    {   // xs tile: LT*64 rows of 32 floats -> ld 36
        const float4* src = (const float4*)(g_xs + (size_t)(n*L_ + l0)*CI_*VP_);
        for (int i = tid; i < LT_*64*8; i += 256) {
            int r = i >> 3, f = i & 7;
            *(float4*)(sm + SM_XS + r*36 + f*4) = src[i];
        }
        // W2: 64 rows of 192 -> ld 196
        const float4* wsrc = (const float4*)g_W2;
        for (int i = tid; i < 64*48; i += 256) {
            int r = i / 48, f = i % 48;
            *(float4*)(sm + SM_W2 + r*196 + f*4) = wsrc[i];
        }
        // Ae: 96 rows of 32 -> ld 36
        const float4* asrc = (const float4*)g_Ae;
        for (int i = tid; i < 96*8; i += 256) {
            int r = i >> 3, f = i & 7;
            *(float4*)(sm + SM_AE + r*36 + f*4) = asrc[i];
        }
        // beff transposed: [w][c]
        for (int i = tid; i < CO_*VP_; i += 256) {
            int c = i >> 5, w = i & 31;
            sm[SM_BF + w*64 + c] = g_beff[i];
        }
        if (tid < 128) sm[SM_ST + tid] = 0.f;
    }
    __syncthreads();

    const int myc = tid & 63;           // fixed channel for stats accumulation
    float csum = 0.f, csum2 = 0.f;

    for (int lt = 0; lt < LT_; lt++) {
        int l = l0 + lt;

        // ---- stage 1: T[(p*64+ci)][w] = xs_l[ci][v] * Ae_p[v][w] ----
        #pragma unroll
        for (int i = 0; i < 3; i++) {
            int t = ww + (i << 3);      // 0..23
            int p = t >> 3, rem = t & 7, ct = rem >> 1, wt = rem & 1;
            wmma::fragment<wmma::matrix_a, 16,16,8, wmma::precision::tf32, wmma::row_major> af;
            wmma::fragment<wmma::matrix_b, 16,16,8, wmma::precision::tf32, wmma::row_major> bf;
            wmma::fragment<wmma::accumulator, 16,16,8, float> cf;
            wmma::fill_fragment(cf, 0.f);
            #pragma unroll
            for (int ks = 0; ks < 4; ks++) {
                wmma::load_matrix_sync(af, sm + SM_XS + (lt*64 + ct*16)*36 + ks*8, 36);
                wmma::load_matrix_sync(bf, sm + SM_AE + (p*32 + ks*8)*36 + wt*16, 36);
                #pragma unroll
                for (int e = 0; e < af.num_elements; e++) af.x[e] = wmma::__float_to_tf32(af.x[e]);
                #pragma unroll
                for (int e = 0; e < bf.num_elements; e++) bf.x[e] = wmma::__float_to_tf32(bf.x[e]);
                wmma::mma_sync(cf, af, bf, cf);
            }
            wmma::store_matrix_sync(sm + SM_T + (p*64 + ct*16)*36 + wt*16, cf, 36,
                                    wmma::mem_row_major);
        }
        __syncthreads();

        // ---- stage 2: U[c][w] = W2[c][k] * T[k][w],  K=192 ----
        {
            int r = ww & 3, cg = ww >> 2;
            wmma::fragment<wmma::matrix_a, 16,16,8, wmma::precision::tf32, wmma::row_major> af;
            wmma::fragment<wmma::matrix_b, 16,16,8, wmma::precision::tf32, wmma::row_major> bf;
            wmma::fragment<wmma::accumulator, 16,16,8, float> cf;
            wmma::fill_fragment(cf, 0.f);
            #pragma unroll
            for (int k8 = 0; k8 < 24; k8++) {
                wmma::load_matrix_sync(af, sm + SM_W2 + (r*16)*196 + k8*8, 196);
                wmma::load_matrix_sync(bf, sm + SM_T + (k8*8)*36 + cg*16, 36);
                #pragma unroll
                for (int e = 0; e < af.num_elements; e++) af.x[e] = wmma::__float_to_tf32(af.x[e]);
                #pragma unroll
                for (int e = 0; e < bf.num_elements; e++) bf.x[e] = wmma::__float_to_tf32(bf.x[e]);
                wmma::mma_sync(cf, af, bf, cf);
            }
            // col-major store: U[w*68 + c]
            wmma::store_matrix_sync(sm + SM_U + (cg*16)*68 + r*16, cf, 68,
                                    wmma::mem_col_major);
        }
        __syncthreads();

        // ---- epilogue: bias*cnt + stats + store u2 ----
        {
            float cnt = (float)((l + 1 < KW_) ? (l + 1) : KW_);
            size_t obase = ((size_t)(n*L_ + l)) * (VP_*CO_);
            for (int j = tid; j < V_*CO_; j += 256) {
                int w = j >> 6, c = j & 63;   // c == myc (stride 256 keeps c fixed)
                float val = sm[SM_U + w*68 + c] + cnt * sm[SM_BF + w*64 + c];
                csum  += val;
                csum2 += val*val;
                g_u2[obase + w*CO_ + c] = val;
            }
        }
        __syncthreads();
    }

    // stats: smem reduce then one global atomic per channel
    atomicAdd(&sm[SM_ST + myc], csum);
    atomicAdd(&sm[SM_ST + 64 + myc], csum2);
    __syncthreads();
    if (tid < CO_) {
        atomicAdd(&g_sum[tid],   sm[SM_ST + tid]);
        atomicAdd(&g_sumsq[tid], sm[SM_ST + 64 + tid]);
    }
}

// ---------------- k3: finalize BN stats ----------------
__global__ void k3_stats(const float* __restrict__ gamma, const float* __restrict__ beta) {
    int c = threadIdx.x;
    if (c < CO_) {
        const float cnt = (float)(N_*L_*V_);
        float mean = g_sum[c] / cnt;
        float var  = g_sumsq[c] / cnt - mean*mean;
        float inv  = rsqrtf(var + 1e-5f);
        float sc   = gamma[c]*inv;
        g_scale[c] = sc;
        g_shift[c] = beta[c] - mean*sc;
    }
}

// ---------------- k4: transpose + BN + relu + residual + relu ----------------
#define K4_SMEM (200*65*4)
__global__ void __launch_bounds__(512) k4_out(const float* __restrict__ x, float* __restrict__ out) {
    extern __shared__ float sm4[];
    int tid = threadIdx.x;
    int n = blockIdx.y, l0 = blockIdx.x * 8;
    for (int i = tid; i < 8*V_*CO_; i += 512) {
        int rr = i >> 6, c = i & 63;
        int l = rr / V_, w = rr % V_;
        sm4[rr*65 + c] = g_u2[(((size_t)(n*L_ + l0 + l))*VP_ + w)*CO_ + c];
    }
    __syncthreads();
    for (int j = tid; j < 8*V_*CO_; j += 512) {
        int c = j / (8*V_), r2 = j % (8*V_);
        int l = r2 / V_, w = r2 % V_;
        float sc = __ldg(&g_scale[c]), sh = __ldg(&g_shift[c]);
        float val = sm4[r2*65 + c]*sc + sh;
        size_t oidx = (((size_t)(n*CO_ + c))*L_ + l0 + l)*V_ + w;
        out[oidx] = fmaxf(fmaxf(val, 0.f) + __ldg(&x[oidx]), 0.f);
    }
}

// ---------------- launch ----------------
extern "C" void kernel_launch(void* const* d_in, const int* in_sizes, int n_in,
                              void* d_out, int out_size) {
    const float* x     = (const float*)d_in[0];
    const float* A     = (const float*)d_in[1];
    const float* edge  = (const float*)d_in[2];
    const float* cw    = (const float*)d_in[3];
    const float* cb    = (const float*)d_in[4];
    const float* gamma = (const float*)d_in[5];
    const float* beta  = (const float*)d_in[6];
    float* out = (float*)d_out;

    cudaFuncSetAttribute(k2_fused, cudaFuncAttributeMaxDynamicSharedMemorySize, SM_FLOATS*4);
    cudaFuncSetAttribute(k4_out,   cudaFuncAttributeMaxDynamicSharedMemorySize, K4_SMEM);

    k0_prep<<<4, 256>>>(A, edge, cw, cb);
    k1_presum<<<(N_*CI_*(L_/CHUNK_)*32 + 255)/256, 256>>>(x);
    k2_fused<<<dim3(L_/LT_, N_), 256, SM_FLOATS*4>>>();
    k3_stats<<<1, 64>>>(gamma, beta);
    k4_out<<<dim3(L_/8, N_), 512, K4_SMEM>>>(x, out);
}

// round 10
// speedup vs baseline: 1.6382x; 1.2556x over previous
#include <cuda_runtime.h>
#include <mma.h>
#include <cstdint>

using namespace nvcuda;

#define N_ 4
#define CI_ 64
#define CO_ 64
#define L_ 1024
#define V_ 25
#define P_ 3
#define VP_ 32
#define KW_ 9
#define K2_ 192      // p*ci contraction dim
#define LT_ 8        // l-values per block in fused kernel

// ---------------- scratch (__device__ globals) ----------------
__device__ float g_u2[N_*L_*VP_*CO_];      // [n][l][w(32)][c] pre-BN activations
__device__ float g_W2[CO_*K2_];            // [c][192k]  (tf32-rounded)
__device__ float g_Ae[P_*VP_*VP_];         // [p][v(32)][w(32)] (tf32-rounded, zero-pad)
__device__ float g_beff[CO_*VP_];          // [c][32w]
__device__ float g_sum[CO_], g_sumsq[CO_], g_scale[CO_], g_shift[CO_];

// ---------------- k0: fold weights (pre-rounded to tf32) ----------------
__global__ void k0_prep(const float* __restrict__ A, const float* __restrict__ edge,
                        const float* __restrict__ cw, const float* __restrict__ cb) {
    int tid = threadIdx.x + blockIdx.x * blockDim.x;
    int nth = blockDim.x * gridDim.x;
    for (int i = tid; i < CO_*K2_; i += nth) {
        int c = i / K2_, k = i % K2_, p = k >> 6, ci = k & 63;
        g_W2[i] = wmma::__float_to_tf32(cw[(p*CO_ + c)*CI_ + ci]);
    }
    for (int i = tid; i < P_*VP_*VP_; i += nth) {
        int p = i / (VP_*VP_), rr = i % (VP_*VP_), v = rr >> 5, w = rr & 31;
        float val = 0.f;
        if (v < V_ && w < V_) { int j = (p*V_ + v)*V_ + w; val = A[j]*edge[j]; }
        g_Ae[i] = wmma::__float_to_tf32(val);
    }
    for (int i = tid; i < CO_*VP_; i += nth) {
        int c = i / VP_, w = i % VP_;
        float s = 0.f;
        if (w < V_)
            for (int p = 0; p < P_; p++) {
                float col = 0.f;
                for (int v = 0; v < V_; v++) { int j = (p*V_+v)*V_+w; col += A[j]*edge[j]; }
                s += cb[p*CO_ + c]*col;
            }
        g_beff[i] = s;
    }
    if (tid < CO_) { g_sum[tid] = 0.f; g_sumsq[tid] = 0.f; }
}

// ---------------- k2: fused presum + double-GEMM (wmma tf32) ----------------
// smem float offsets (lds ≡ 4 mod 32)
#define SM_XS 0                         // [8l*64ci][ld 36]   18432
#define SM_W2 18432                     // [64c][ld 196]      12544
#define SM_AE 30976                     // [96 (p,v)][ld 36]   3456
#define SM_T  34432                     // [192k][ld 68]      13056  (2 l's of w-cols)
#define SM_U  47488                     // [64 ncol][ld 68]    4352
#define SM_BF 51840                     // [32w][64c]          2048
#define SM_ST 53888                     // stats               128
#define SM_FLOATS 54016                 // 216064 bytes

__global__ void __launch_bounds__(256, 1) k2_fused(const float* __restrict__ x) {
    extern __shared__ float sm[];
    int tid = threadIdx.x, ww = tid >> 5;
    int n = blockIdx.y, l0 = blockIdx.x * LT_;

    // ---- load weights / bias ----
    {
        const float4* wsrc = (const float4*)g_W2;
        for (int i = tid; i < 64*48; i += 256) {
            int r = i / 48, f = i % 48;
            *(float4*)(sm + SM_W2 + r*196 + f*4) = wsrc[i];
        }
        const float4* asrc = (const float4*)g_Ae;
        for (int i = tid; i < 96*8; i += 256) {
            int r = i >> 3, f = i & 7;
            *(float4*)(sm + SM_AE + r*36 + f*4) = asrc[i];
        }
        for (int i = tid; i < CO_*VP_; i += 256) {
            int c = i >> 5, w = i & 31;
            sm[SM_BF + w*64 + c] = g_beff[i];
        }
        if (tid < 128) sm[SM_ST + tid] = 0.f;
    }

    // ---- fused temporal presum: xs[(lt,ci)][v] = sum_{j=l-8..l} x[n,ci,j,v] ----
    for (int it = 0; it < 8; it++) {
        int pair = tid + it*256;            // 2048 (ci,v) pairs
        int ci = pair >> 5, v = pair & 31;
        if (v >= V_) {
            #pragma unroll
            for (int lt = 0; lt < LT_; lt++) sm[SM_XS + (lt*64 + ci)*36 + v] = 0.f;
            continue;
        }
        const float* xb = x + ((size_t)(n*CI_ + ci)*L_)*V_ + v;
        float vals[16];
        #pragma unroll
        for (int i = 0; i < 16; i++) {
            int l = l0 - 8 + i;
            vals[i] = (l >= 0) ? xb[(size_t)l*V_] : 0.f;
        }
        float s = 0.f;
        #pragma unroll
        for (int i = 0; i < 8; i++) s += vals[i];
        #pragma unroll
        for (int j = 0; j < LT_; j++) {
            s += vals[j + 8];               // window [l-8, l], clamped at 0
            sm[SM_XS + (j*64 + ci)*36 + v] = wmma::__float_to_tf32(s);
            s -= vals[j];
        }
    }
    __syncthreads();

    const int myc = tid & 63;
    float csum = 0.f, csum2 = 0.f;

    for (int ltp = 0; ltp < LT_/2; ltp++) {
        // ---- stage 1: T[(p*64+ci)][half*32+w] = xs_l[ci][v] * Ae_p[v][w] ----
        {
            int ct = ww & 3, half = ww >> 2;
            int lt = ltp*2 + half;
            wmma::fragment<wmma::matrix_a, 16,16,8, wmma::precision::tf32, wmma::row_major> af;
            wmma::fragment<wmma::matrix_b, 16,16,8, wmma::precision::tf32, wmma::row_major> bf;
            wmma::fragment<wmma::accumulator, 16,16,8, float> cf[6];   // (p, wt)
            #pragma unroll
            for (int t = 0; t < 6; t++) wmma::fill_fragment(cf[t], 0.f);
            #pragma unroll
            for (int ks = 0; ks < 4; ks++) {
                wmma::load_matrix_sync(af, sm + SM_XS + (lt*64 + ct*16)*36 + ks*8, 36);
                #pragma unroll
                for (int p = 0; p < P_; p++) {
                    #pragma unroll
                    for (int wt = 0; wt < 2; wt++) {
                        wmma::load_matrix_sync(bf, sm + SM_AE + (p*32 + ks*8)*36 + wt*16, 36);
                        wmma::mma_sync(cf[p*2 + wt], af, bf, cf[p*2 + wt]);
                    }
                }
            }
            #pragma unroll
            for (int p = 0; p < P_; p++)
                #pragma unroll
                for (int wt = 0; wt < 2; wt++) {
                    #pragma unroll
                    for (int e = 0; e < cf[0].num_elements; e++)
                        cf[p*2+wt].x[e] = wmma::__float_to_tf32(cf[p*2+wt].x[e]);
                    wmma::store_matrix_sync(sm + SM_T + (p*64 + ct*16)*68 + half*32 + wt*16,
                                            cf[p*2+wt], 68, wmma::mem_row_major);
                }
        }
        __syncthreads();

        // ---- stage 2: U[c][ncol] = W2[c][k] * T[k][ncol], K=192, N=64 ----
        {
            int r = ww & 3, ng = ww >> 2;
            wmma::fragment<wmma::matrix_a, 16,16,8, wmma::precision::tf32, wmma::row_major> af;
            wmma::fragment<wmma::matrix_b, 16,16,8, wmma::precision::tf32, wmma::row_major> bf;
            wmma::fragment<wmma::accumulator, 16,16,8, float> cf[2];
            wmma::fill_fragment(cf[0], 0.f);
            wmma::fill_fragment(cf[1], 0.f);
            #pragma unroll
            for (int k8 = 0; k8 < 24; k8++) {
                wmma::load_matrix_sync(af, sm + SM_W2 + (r*16)*196 + k8*8, 196);
                #pragma unroll
                for (int j = 0; j < 2; j++) {
                    wmma::load_matrix_sync(bf, sm + SM_T + (k8*8)*68 + (ng*2 + j)*16, 68);
                    wmma::mma_sync(cf[j], af, bf, cf[j]);
                }
            }
            #pragma unroll
            for (int j = 0; j < 2; j++)
                wmma::store_matrix_sync(sm + SM_U + ((ng*2 + j)*16)*68 + r*16, cf[j], 68,
                                        wmma::mem_col_major);
        }
        __syncthreads();

        // ---- epilogue: bias*cnt + stats + store u2 (both l's of the pair) ----
        for (int j = tid; j < 2*V_*CO_; j += 256) {
            int half = j / (V_*CO_);
            int r2 = j % (V_*CO_);
            int w = r2 >> 6, c = r2 & 63;        // c == myc (stride 256)
            int l = l0 + ltp*2 + half;
            float cnt = (float)((l + 1 < KW_) ? (l + 1) : KW_);
            float val = sm[SM_U + (half*32 + w)*68 + c] + cnt * sm[SM_BF + w*64 + c];
            csum  += val;
            csum2 += val*val;
            g_u2[(((size_t)(n*L_ + l))*VP_ + w)*CO_ + c] = val;
        }
        __syncthreads();
    }

    // stats: smem reduce then one global atomic per channel
    atomicAdd(&sm[SM_ST + myc], csum);
    atomicAdd(&sm[SM_ST + 64 + myc], csum2);
    __syncthreads();
    if (tid < CO_) {
        atomicAdd(&g_sum[tid],   sm[SM_ST + tid]);
        atomicAdd(&g_sumsq[tid], sm[SM_ST + 64 + tid]);
    }
}

// ---------------- k3: finalize BN stats ----------------
__global__ void k3_stats(const float* __restrict__ gamma, const float* __restrict__ beta) {
    int c = threadIdx.x;
    if (c < CO_) {
        const float cnt = (float)(N_*L_*V_);
        float mean = g_sum[c] / cnt;
        float var  = g_sumsq[c] / cnt - mean*mean;
        float inv  = rsqrtf(var + 1e-5f);
        float sc   = gamma[c]*inv;
        g_scale[c] = sc;
        g_shift[c] = beta[c] - mean*sc;
    }
}

// ---------------- k4: transpose + BN + relu + residual + relu ----------------
#define K4_SMEM (200*65*4)
__global__ void __launch_bounds__(512) k4_out(const float* __restrict__ x, float* __restrict__ out) {
    extern __shared__ float sm4[];
    int tid = threadIdx.x;
    int n = blockIdx.y, l0 = blockIdx.x * 8;
    for (int i = tid; i < 8*V_*CO_; i += 512) {
        int rr = i >> 6, c = i & 63;
        int l = rr / V_, w = rr % V_;
        sm4[rr*65 + c] = g_u2[(((size_t)(n*L_ + l0 + l))*VP_ + w)*CO_ + c];
    }
    __syncthreads();
    for (int j = tid; j < 8*V_*CO_; j += 512) {
        int c = j / (8*V_), r2 = j % (8*V_);
        int l = r2 / V_, w = r2 % V_;
        float sc = __ldg(&g_scale[c]), sh = __ldg(&g_shift[c]);
        float val = sm4[r2*65 + c]*sc + sh;
        size_t oidx = (((size_t)(n*CO_ + c))*L_ + l0 + l)*V_ + w;
        out[oidx] = fmaxf(fmaxf(val, 0.f) + __ldg(&x[oidx]), 0.f);
    }
}

// ---------------- launch ----------------
extern "C" void kernel_launch(void* const* d_in, const int* in_sizes, int n_in,
                              void* d_out, int out_size) {
    const float* x     = (const float*)d_in[0];
    const float* A     = (const float*)d_in[1];
    const float* edge  = (const float*)d_in[2];
    const float* cw    = (const float*)d_in[3];
    const float* cb    = (const float*)d_in[4];
    const float* gamma = (const float*)d_in[5];
    const float* beta  = (const float*)d_in[6];
    float* out = (float*)d_out;

    cudaFuncSetAttribute(k2_fused, cudaFuncAttributeMaxDynamicSharedMemorySize, SM_FLOATS*4);
    cudaFuncSetAttribute(k4_out,   cudaFuncAttributeMaxDynamicSharedMemorySize, K4_SMEM);

    k0_prep<<<4, 256>>>(A, edge, cw, cb);
    k2_fused<<<dim3(L_/LT_, N_), 256, SM_FLOATS*4>>>(x);
    k3_stats<<<1, 64>>>(gamma, beta);
    k4_out<<<dim3(L_/8, N_), 512, K4_SMEM>>>(x, out);
}

// round 11
// speedup vs baseline: 2.1192x; 1.2936x over previous
#include <cuda_runtime.h>
#include <mma.h>
#include <cstdint>

using namespace nvcuda;

#define N_ 4
#define CI_ 64
#define CO_ 64
#define L_ 1024
#define V_ 25
#define P_ 3
#define VP_ 32
#define KW_ 9
#define K2_ 192
#define LT_ 4        // l-values per block in fused kernel

// ---------------- scratch (__device__ globals) ----------------
__device__ float g_u2[N_*L_*VP_*CO_];      // [n][l][w(32)][c] pre-BN activations
__device__ float g_W2[CO_*K2_];            // [c][192k]  (tf32-rounded)
__device__ float g_Ae[P_*VP_*VP_];         // [p][v(32)][w(32)] (tf32-rounded, zero-pad)
__device__ float g_beff[CO_*VP_];          // [c][32w]
__device__ float g_sum[CO_], g_sumsq[CO_], g_scale[CO_], g_shift[CO_];

// ---------------- k0: fold weights (pre-rounded to tf32) ----------------
__global__ void k0_prep(const float* __restrict__ A, const float* __restrict__ edge,
                        const float* __restrict__ cw, const float* __restrict__ cb) {
    int tid = threadIdx.x + blockIdx.x * blockDim.x;
    int nth = blockDim.x * gridDim.x;
    for (int i = tid; i < CO_*K2_; i += nth) {
        int c = i / K2_, k = i % K2_, p = k >> 6, ci = k & 63;
        g_W2[i] = wmma::__float_to_tf32(cw[(p*CO_ + c)*CI_ + ci]);
    }
    for (int i = tid; i < P_*VP_*VP_; i += nth) {
        int p = i / (VP_*VP_), rr = i % (VP_*VP_), v = rr >> 5, w = rr & 31;
        float val = 0.f;
        if (v < V_ && w < V_) { int j = (p*V_ + v)*V_ + w; val = A[j]*edge[j]; }
        g_Ae[i] = wmma::__float_to_tf32(val);
    }
    for (int i = tid; i < CO_*VP_; i += nth) {
        int c = i / VP_, w = i % VP_;
        float s = 0.f;
        if (w < V_)
            for (int p = 0; p < P_; p++) {
                float col = 0.f;
                for (int v = 0; v < V_; v++) { int j = (p*V_+v)*V_+w; col += A[j]*edge[j]; }
                s += cb[p*CO_ + c]*col;
            }
        g_beff[i] = s;
    }
    if (tid < CO_) { g_sum[tid] = 0.f; g_sumsq[tid] = 0.f; }
}

// ---------------- k2: fused presum + double-GEMM, 2 blocks/SM ----------------
// smem float offsets (lds ≡ 4 mod 32). W2 staged transiently in [0, 12544).
#define SM_XS 0                         // [4l*64ci][ld 36]    9216
#define SM_T  9216                      // [192k][ld 36]       6912
#define SM_AE 16128                     // [96 (p,v)][ld 36]   3456
#define SM_U  19584                     // 2 x [32w][ld 68]    4352
#define SM_BF 23936                     // [32w][64c]          2048
#define SM_ST 25984                     // stats                128
#define SM_FLOATS 26112                 // 104448 bytes

__global__ void __launch_bounds__(256, 2) k2_fused(const float* __restrict__ x) {
    extern __shared__ float sm[];
    int tid = threadIdx.x, ww = tid >> 5;
    int n = blockIdx.y, l0 = blockIdx.x * LT_;

    // ---- phase 0: stage W2 into smem (transient, ld 196 over XS+T space) ----
    {
        const float4* wsrc = (const float4*)g_W2;
        for (int i = tid; i < 64*48; i += 256) {
            int r = i / 48, f = i % 48;
            *(float4*)(sm + r*196 + f*4) = wsrc[i];
        }
        const float4* asrc = (const float4*)g_Ae;
        for (int i = tid; i < 96*8; i += 256) {
            int r = i >> 3, f = i & 7;
            *(float4*)(sm + SM_AE + r*36 + f*4) = asrc[i];
        }
        for (int i = tid; i < CO_*VP_; i += 256) {
            int c = i >> 5, w = i & 31;
            sm[SM_BF + w*64 + c] = g_beff[i];
        }
        if (tid < 128) sm[SM_ST + tid] = 0.f;
    }
    __syncthreads();

    // ---- phase 1: register-cache this warp's stage-2 A fragments (W2) ----
    const int r_s2 = ww & 3;            // c-tile row
    const int kh   = ww >> 2;           // K half (0: k8 0-11, 1: k8 12-23)
    wmma::fragment<wmma::matrix_a, 16,16,8, wmma::precision::tf32, wmma::row_major> afc[12];
    #pragma unroll
    for (int k8 = 0; k8 < 12; k8++)
        wmma::load_matrix_sync(afc[k8], sm + (r_s2*16)*196 + (kh*12 + k8)*8, 196);
    __syncthreads();                    // frags in regs; staging area may be reused

    // ---- phase 2: fused temporal presum -> XS (tf32-rounded) ----
    for (int it = 0; it < 8; it++) {
        int pair = tid + it*256;        // 2048 (ci,v) pairs
        int ci = pair >> 5, v = pair & 31;
        if (v >= V_) {
            #pragma unroll
            for (int lt = 0; lt < LT_; lt++) sm[SM_XS + (lt*64 + ci)*36 + v] = 0.f;
            continue;
        }
        const float* xb = x + ((size_t)(n*CI_ + ci)*L_)*V_ + v;
        float vals[KW_ - 1 + LT_];      // 12
        #pragma unroll
        for (int i = 0; i < KW_ - 1 + LT_; i++) {
            int l = l0 - (KW_ - 1) + i;
            vals[i] = (l >= 0) ? xb[(size_t)l*V_] : 0.f;
        }
        float s = 0.f;
        #pragma unroll
        for (int i = 0; i < KW_ - 1; i++) s += vals[i];
        #pragma unroll
        for (int j = 0; j < LT_; j++) {
            s += vals[j + KW_ - 1];
            sm[SM_XS + (j*64 + ci)*36 + v] = wmma::__float_to_tf32(s);
            s -= vals[j];
        }
    }
    __syncthreads();

    const int myc = tid & 63;
    float csum = 0.f, csum2 = 0.f;

    for (int lt = 0; lt < LT_; lt++) {
        // ---- stage 1: T[(p*64+ci)][w] = xs_lt[ci][v] * Ae_p[v][w] ----
        {
            int ct = ww & 3, h = ww >> 2;   // h: which 3 of the 6 (p,wt) tiles
            wmma::fragment<wmma::matrix_a, 16,16,8, wmma::precision::tf32, wmma::row_major> af;
            wmma::fragment<wmma::matrix_b, 16,16,8, wmma::precision::tf32, wmma::row_major> bf;
            wmma::fragment<wmma::accumulator, 16,16,8, float> cf[3];
            #pragma unroll
            for (int q = 0; q < 3; q++) wmma::fill_fragment(cf[q], 0.f);
            #pragma unroll
            for (int ks = 0; ks < 4; ks++) {
                wmma::load_matrix_sync(af, sm + SM_XS + (lt*64 + ct*16)*36 + ks*8, 36);
                #pragma unroll
                for (int q = 0; q < 3; q++) {
                    int idx = h*3 + q, p = idx >> 1, wt = idx & 1;
                    wmma::load_matrix_sync(bf, sm + SM_AE + (p*32 + ks*8)*36 + wt*16, 36);
                    wmma::mma_sync(cf[q], af, bf, cf[q]);
                }
            }
            #pragma unroll
            for (int q = 0; q < 3; q++) {
                int idx = h*3 + q, p = idx >> 1, wt = idx & 1;
                #pragma unroll
                for (int e = 0; e < cf[0].num_elements; e++)
                    cf[q].x[e] = wmma::__float_to_tf32(cf[q].x[e]);
                wmma::store_matrix_sync(sm + SM_T + (p*64 + ct*16)*36 + wt*16,
                                        cf[q], 36, wmma::mem_row_major);
            }
        }
        __syncthreads();

        // ---- stage 2: U_kh[c][w] = sum_{k in half} W2[c][k] * T[k][w] ----
        {
            wmma::fragment<wmma::matrix_b, 16,16,8, wmma::precision::tf32, wmma::row_major> bf;
            wmma::fragment<wmma::accumulator, 16,16,8, float> cf[2];
            wmma::fill_fragment(cf[0], 0.f);
            wmma::fill_fragment(cf[1], 0.f);
            #pragma unroll
            for (int k8 = 0; k8 < 12; k8++) {
                #pragma unroll
                for (int ng = 0; ng < 2; ng++) {
                    wmma::load_matrix_sync(bf, sm + SM_T + ((kh*12 + k8)*8)*36 + ng*16, 36);
                    wmma::mma_sync(cf[ng], afc[k8], bf, cf[ng]);
                }
            }
            #pragma unroll
            for (int ng = 0; ng < 2; ng++)
                wmma::store_matrix_sync(sm + SM_U + kh*2176 + (ng*16)*68 + r_s2*16,
                                        cf[ng], 68, wmma::mem_col_major);
        }
        __syncthreads();

        // ---- epilogue: add K-halves + bias*cnt + stats + store u2 ----
        {
            int l = l0 + lt;
            float cnt = (float)((l + 1 < KW_) ? (l + 1) : KW_);
            size_t obase = ((size_t)(n*L_ + l)) * (VP_*CO_);
            for (int j = tid; j < V_*CO_; j += 256) {
                int w = j >> 6, c = j & 63;           // c == myc (stride 256)
                float val = sm[SM_U + w*68 + c] + sm[SM_U + 2176 + w*68 + c]
                          + cnt * sm[SM_BF + w*64 + c];
                csum  += val;
                csum2 += val*val;
                g_u2[obase + w*CO_ + c] = val;
            }
        }
        // no barrier needed here: next stage1 touches only XS/AE/T;
        // sync after stage1 guards U reuse.
    }

    atomicAdd(&sm[SM_ST + myc], csum);
    atomicAdd(&sm[SM_ST + 64 + myc], csum2);
    __syncthreads();
    if (tid < CO_) {
        atomicAdd(&g_sum[tid],   sm[SM_ST + tid]);
        atomicAdd(&g_sumsq[tid], sm[SM_ST + 64 + tid]);
    }
}

// ---------------- k3: finalize BN stats ----------------
__global__ void k3_stats(const float* __restrict__ gamma, const float* __restrict__ beta) {
    int c = threadIdx.x;
    if (c < CO_) {
        const float cnt = (float)(N_*L_*V_);
        float mean = g_sum[c] / cnt;
        float var  = g_sumsq[c] / cnt - mean*mean;
        float inv  = rsqrtf(var + 1e-5f);
        float sc   = gamma[c]*inv;
        g_scale[c] = sc;
        g_shift[c] = beta[c] - mean*sc;
    }
}

// ---------------- k4: transpose + BN + relu + residual + relu ----------------
// store phase: thread (c = tid>>3, rg = tid&7), fixed c -> scale/shift hoisted.
#define K4_SMEM (200*65*4)
__global__ void __launch_bounds__(512) k4_out(const float* __restrict__ x, float* __restrict__ out) {
    extern __shared__ float sm4[];
    int tid = threadIdx.x;
    int n = blockIdx.y, l0 = blockIdx.x * 8;
    for (int i = tid; i < 8*V_*CO_; i += 512) {
        int rr = i >> 6, c = i & 63;
        int l = rr / V_, w = rr % V_;
        sm4[rr*65 + c] = g_u2[(((size_t)(n*L_ + l0 + l))*VP_ + w)*CO_ + c];
    }
    __syncthreads();
    {
        int c = tid >> 3, rg = tid & 7;
        float sc = g_scale[c], sh = g_shift[c];
        const float* xc = x   + ((size_t)(n*CO_ + c)*L_ + l0)*V_;
        float*       oc = out + ((size_t)(n*CO_ + c)*L_ + l0)*V_;
        #pragma unroll
        for (int i = 0; i < V_; i++) {
            int rr = i*8 + rg;                 // 0..199, 8 consecutive per i
            float val = sm4[rr*65 + c]*sc + sh;
            oc[rr] = fmaxf(fmaxf(val, 0.f) + xc[rr], 0.f);
        }
    }
}

// ---------------- launch ----------------
extern "C" void kernel_launch(void* const* d_in, const int* in_sizes, int n_in,
                              void* d_out, int out_size) {
    const float* x     = (const float*)d_in[0];
    const float* A     = (const float*)d_in[1];
    const float* edge  = (const float*)d_in[2];
    const float* cw    = (const float*)d_in[3];
    const float* cb    = (const float*)d_in[4];
    const float* gamma = (const float*)d_in[5];
    const float* beta  = (const float*)d_in[6];
    float* out = (float*)d_out;

    cudaFuncSetAttribute(k2_fused, cudaFuncAttributeMaxDynamicSharedMemorySize, SM_FLOATS*4);
    cudaFuncSetAttribute(k4_out,   cudaFuncAttributeMaxDynamicSharedMemorySize, K4_SMEM);

    k0_prep<<<4, 256>>>(A, edge, cw, cb);
    k2_fused<<<dim3(L_/LT_, N_), 256, SM_FLOATS*4>>>(x);
    k3_stats<<<1, 64>>>(gamma, beta);
    k4_out<<<dim3(L_/8, N_), 512, K4_SMEM>>>(x, out);
}

// round 12
// speedup vs baseline: 3.4365x; 1.6216x over previous
#include <cuda_runtime.h>
#include <cuda_fp16.h>
#include <cstdint>

#define N_ 4
#define CI_ 64
#define CO_ 64
#define L_ 1024
#define V_ 25
#define P_ 3
#define VP_ 32
#define KW_ 9
#define K2_ 192
#define LT_ 4

// ---------------- scratch (__device__ globals) ----------------
__device__ float  g_u2[N_*L_*V_*CO_];                 // [n][l][w25][c] dense pre-BN
__device__ __align__(16) __half g_W2h[64*200];        // [c64][200]  (k=p*64+ci, pad)
__device__ __align__(16) __half g_Aeh[96*40];         // [(p,v)96][40w]
__device__ float  g_bf2[VP_*CO_];                     // [w32][c64]
__device__ float  g_sum[CO_], g_sumsq[CO_], g_scale[CO_], g_shift[CO_];

// ---------------- PTX primitives ----------------
__device__ __forceinline__ uint32_t smem_u32(const void* p) {
    uint32_t a;
    asm("{ .reg .u64 t; cvta.to.shared.u64 t, %1; cvt.u32.u64 %0, t; }" : "=r"(a) : "l"(p));
    return a;
}
#define LDSM4(r, addr) \
    asm volatile("ldmatrix.sync.aligned.m8n8.x4.shared.b16 {%0,%1,%2,%3}, [%4];" \
        : "=r"((r)[0]), "=r"((r)[1]), "=r"((r)[2]), "=r"((r)[3]) : "r"(addr))
#define LDSM4T(r, addr) \
    asm volatile("ldmatrix.sync.aligned.m8n8.x4.trans.shared.b16 {%0,%1,%2,%3}, [%4];" \
        : "=r"((r)[0]), "=r"((r)[1]), "=r"((r)[2]), "=r"((r)[3]) : "r"(addr))
#define MMA16816(d, a, b0, b1) \
    asm volatile("mma.sync.aligned.m16n8k16.row.col.f32.f16.f16.f32 " \
        "{%0,%1,%2,%3}, {%4,%5,%6,%7}, {%8,%9}, {%0,%1,%2,%3};" \
        : "+f"((d)[0]), "+f"((d)[1]), "+f"((d)[2]), "+f"((d)[3]) \
        : "r"((a)[0]), "r"((a)[1]), "r"((a)[2]), "r"((a)[3]), "r"(b0), "r"(b1))

// ---------------- k0: fold weights into fp16 / final layouts ----------------
__global__ void k0_prep(const float* __restrict__ A, const float* __restrict__ edge,
                        const float* __restrict__ cw, const float* __restrict__ cb) {
    int tid = threadIdx.x + blockIdx.x * blockDim.x;
    int nth = blockDim.x * gridDim.x;
    for (int i = tid; i < 64*200; i += nth) {
        int c = i / 200, k = i % 200;
        float val = 0.f;
        if (k < K2_) { int p = k >> 6, ci = k & 63; val = cw[(p*CO_ + c)*CI_ + ci]; }
        g_W2h[i] = __float2half(val);
    }
    for (int i = tid; i < 96*40; i += nth) {
        int row = i / 40, w = i % 40, p = row >> 5, v = row & 31;
        float val = 0.f;
        if (v < V_ && w < V_) { int j = (p*V_ + v)*V_ + w; val = A[j]*edge[j]; }
        g_Aeh[i] = __float2half(val);
    }
    for (int i = tid; i < VP_*CO_; i += nth) {
        int w = i >> 6, c = i & 63;
        float s = 0.f;
        if (w < V_)
            for (int p = 0; p < P_; p++) {
                float col = 0.f;
                for (int v = 0; v < V_; v++) { int j = (p*V_+v)*V_+w; col += A[j]*edge[j]; }
                s += cb[p*CO_ + c]*col;
            }
        g_bf2[i] = s;
    }
    if (tid < CO_) { g_sum[tid] = 0.f; g_sumsq[tid] = 0.f; }
}

// ---------------- k2: fused presum + double fp16 GEMM, 3 blocks/SM ----------------
// byte offsets into dynamic smem (char)
#define SB_XS 0                         // half [256(lt,ci)][40v]    20480
#define SB_T  20480                     // half [192k][40w]          15360
#define SB_AE 35840                     // half [96(p,v)][40w]        7680
#define SB_U  43520                     // f32 2kh x [32w][68 c-ld]  17408
#define SB_BF 60928                     // f32 [32w][64c]             8192
#define SB_ST 69120                     // f32 stats 128               512
#define SB_TOTAL 69632                  // 68 KB -> 3 blocks/SM
// W2 staging (transient): [64][200] half = 51200 B over [0, 51200) (XS+T+part of U)

__global__ void __launch_bounds__(256, 3) k2_fused(const float* __restrict__ x) {
    extern __shared__ char sm[];
    const uint32_t sbase = smem_u32(sm);
    int tid = threadIdx.x, ww = tid >> 5, lane = tid & 31;
    int n = blockIdx.y, l0 = blockIdx.x * LT_;
    const int group = lane >> 2, tq = lane & 3;

    // ldmatrix per-lane byte offsets (quad -> 8x8 block pattern)
    const uint32_t ldsm40  = ((lane & 7) + ((lane >> 3) & 1) * 8) * 80
                           + ((lane >> 4) & 1) * 16;
    const uint32_t ldsm200 = ((lane & 7) + ((lane >> 3) & 1) * 8) * 400
                           + ((lane >> 4) & 1) * 16;

    // ---- phase 0: stage W2 into smem[0..51200); load BF; zero stats ----
    {
        const float4* wsrc = (const float4*)g_W2h;
        float4* wdst = (float4*)sm;
        for (int i = tid; i < 3200; i += 256) wdst[i] = wsrc[i];
        const float4* bsrc = (const float4*)g_bf2;
        float4* bdst = (float4*)(sm + SB_BF);
        for (int i = tid; i < 512; i += 256) bdst[i] = bsrc[i];
        float* st = (float*)(sm + SB_ST);
        if (tid < 128) st[tid] = 0.f;
    }
    __syncthreads();

    // ---- phase 1: cache this warp's stage-2 A fragments (24 regs) ----
    const int r_s2 = ww & 3;            // c-tile
    const int kh   = ww >> 2;           // K half: k-steps kh*6 .. kh*6+5
    uint32_t wf[6][4];
    #pragma unroll
    for (int i = 0; i < 6; i++)
        LDSM4(wf[i], sbase + (uint32_t)((r_s2*16)*200 + (kh*6 + i)*16)*2 + ldsm200);
    __syncthreads();                    // staging area free after this

    // ---- phase 2: AE copy + fused temporal presum -> XS (half) ----
    {
        const float4* asrc = (const float4*)g_Aeh;
        float4* adst = (float4*)(sm + SB_AE);
        for (int i = tid; i < 480; i += 256) adst[i] = asrc[i];
    }
    __half* xs = (__half*)(sm + SB_XS);
    for (int it = 0; it < 8; it++) {
        int pair = tid + it*256;        // 2048 (ci, v)
        int ci = pair >> 5, v = pair & 31;
        if (v >= V_) {
            #pragma unroll
            for (int j = 0; j < LT_; j++) xs[(j*64 + ci)*40 + v] = __float2half(0.f);
            continue;
        }
        const float* xb = x + ((size_t)(n*CI_ + ci)*L_)*V_ + v;
        float vals[KW_ - 1 + LT_];
        #pragma unroll
        for (int i = 0; i < KW_ - 1 + LT_; i++) {
            int l = l0 - (KW_ - 1) + i;
            vals[i] = (l >= 0) ? xb[(size_t)l*V_] : 0.f;
        }
        float s = 0.f;
        #pragma unroll
        for (int i = 0; i < KW_ - 1; i++) s += vals[i];
        #pragma unroll
        for (int j = 0; j < LT_; j++) {
            s += vals[j + KW_ - 1];
            xs[(j*64 + ci)*40 + v] = __float2half(s);
            s -= vals[j];
        }
    }
    __syncthreads();

    const int myc = tid & 63;
    float csum = 0.f, csum2 = 0.f;
    float* Uf = (float*)(sm + SB_U);
    const float* BF = (const float*)(sm + SB_BF);

    for (int lt = 0; lt < LT_; lt++) {
        // ---- stage 1: T[(p*64+ci)][w] = xs_lt[ci][v] * Ae_p[v][w] ----
        {
            int ct = ww & 3, h = ww >> 2;
            uint32_t a[2][4];
            #pragma unroll
            for (int ks = 0; ks < 2; ks++)
                LDSM4(a[ks], sbase + SB_XS
                      + (uint32_t)((lt*64 + ct*16)*40 + ks*16)*2 + ldsm40);
            #pragma unroll
            for (int q = 0; q < 3; q++) {
                int idx = h*3 + q, p = idx >> 1, wt = idx & 1;
                float d[2][4] = {{0.f,0.f,0.f,0.f},{0.f,0.f,0.f,0.f}};
                #pragma unroll
                for (int ks = 0; ks < 2; ks++) {
                    uint32_t b[4];
                    LDSM4T(b, sbase + SB_AE
                           + (uint32_t)((p*32 + ks*16)*40 + wt*16)*2 + ldsm40);
                    MMA16816(d[0], a[ks], b[0], b[1]);
                    MMA16816(d[1], a[ks], b[2], b[3]);
                }
                #pragma unroll
                for (int j = 0; j < 2; j++) {
                    int wcol = wt*16 + j*8 + tq*2;
                    int row  = p*64 + ct*16 + group;
                    *(__half2*)(sm + SB_T + (row*40 + wcol)*2)
                        = __floats2half2_rn(d[j][0], d[j][1]);
                    *(__half2*)(sm + SB_T + ((row + 8)*40 + wcol)*2)
                        = __floats2half2_rn(d[j][2], d[j][3]);
                }
            }
        }
        __syncthreads();

        // ---- stage 2: U_kh[c][w] = sum_{k in half} W2[c][k] * T[k][w] ----
        {
            float e[4][4] = {{0.f,0.f,0.f,0.f},{0.f,0.f,0.f,0.f},
                             {0.f,0.f,0.f,0.f},{0.f,0.f,0.f,0.f}};
            #pragma unroll
            for (int i = 0; i < 6; i++) {
                uint32_t b0[4], b1[4];
                uint32_t tb = sbase + SB_T + (uint32_t)(((kh*6 + i)*16)*40)*2 + ldsm40;
                LDSM4T(b0, tb);
                LDSM4T(b1, tb + 32);    // col0 = 16 halves = 32 B
                MMA16816(e[0], wf[i], b0[0], b0[1]);
                MMA16816(e[1], wf[i], b0[2], b0[3]);
                MMA16816(e[2], wf[i], b1[0], b1[1]);
                MMA16816(e[3], wf[i], b1[2], b1[3]);
            }
            float* U = Uf + kh*2176;
            #pragma unroll
            for (int j = 0; j < 4; j++) {
                int w0 = j*8 + tq*2;
                int c0 = r_s2*16 + group;
                U[w0*68 + c0]           = e[j][0];
                U[(w0 + 1)*68 + c0]     = e[j][1];
                U[w0*68 + c0 + 8]       = e[j][2];
                U[(w0 + 1)*68 + c0 + 8] = e[j][3];
            }
        }
        __syncthreads();

        // ---- epilogue: sum K halves + bias*cnt + stats + store dense u2 ----
        {
            int l = l0 + lt;
            float cnt = (float)((l + 1 < KW_) ? (l + 1) : KW_);
            float* ug = g_u2 + (size_t)(n*L_ + l)*(V_*CO_);
            for (int j = tid; j < V_*CO_; j += 256) {
                int w = j >> 6, c = j & 63;          // c == myc
                float val = Uf[w*68 + c] + Uf[2176 + w*68 + c] + cnt*BF[w*64 + c];
                csum  += val;
                csum2 += val*val;
                ug[j] = val;
            }
        }
        // no barrier: next stage1 writes T only; its post-stage1 sync orders U/epi.
    }

    float* st = (float*)(sm + SB_ST);
    atomicAdd(&st[myc], csum);
    atomicAdd(&st[64 + myc], csum2);
    __syncthreads();
    if (tid < CO_) {
        atomicAdd(&g_sum[tid],   st[tid]);
        atomicAdd(&g_sumsq[tid], st[64 + tid]);
    }
}

// ---------------- k3: finalize BN stats ----------------
__global__ void k3_stats(const float* __restrict__ gamma, const float* __restrict__ beta) {
    int c = threadIdx.x;
    if (c < CO_) {
        const float cnt = (float)(N_*L_*V_);
        float mean = g_sum[c] / cnt;
        float var  = g_sumsq[c] / cnt - mean*mean;
        float inv  = rsqrtf(var + 1e-5f);
        float sc   = gamma[c]*inv;
        g_scale[c] = sc;
        g_shift[c] = beta[c] - mean*sc;
    }
}

// ---------------- k4: transpose + BN + relu + residual + relu ----------------
#define K4_SMEM (200*65*4)
__global__ void __launch_bounds__(512) k4_out(const float* __restrict__ x, float* __restrict__ out) {
    extern __shared__ float sm4[];
    int tid = threadIdx.x, wid = tid >> 5, lane = tid & 31;
    int n = blockIdx.y, l0 = blockIdx.x * 8;
    for (int l = 0; l < 8; l++) {
        const float* src = g_u2 + (size_t)(n*L_ + l0 + l)*(V_*CO_);
        for (int i = tid; i < V_*CO_; i += 512) {
            int w = i >> 6, c = i & 63;
            sm4[(l*V_ + w)*65 + c] = src[i];
        }
    }
    __syncthreads();
    for (int c = wid; c < CO_; c += 16) {
        float sc = g_scale[c], sh = g_shift[c];
        const float* xc = x   + ((size_t)(n*CO_ + c)*L_ + l0)*V_;
        float*       oc = out + ((size_t)(n*CO_ + c)*L_ + l0)*V_;
        for (int rr = lane; rr < 8*V_; rr += 32) {
            float val = sm4[rr*65 + c]*sc + sh;
            oc[rr] = fmaxf(fmaxf(val, 0.f) + xc[rr], 0.f);
        }
    }
}

// ---------------- launch ----------------
extern "C" void kernel_launch(void* const* d_in, const int* in_sizes, int n_in,
                              void* d_out, int out_size) {
    const float* x     = (const float*)d_in[0];
    const float* A     = (const float*)d_in[1];
    const float* edge  = (const float*)d_in[2];
    const float* cw    = (const float*)d_in[3];
    const float* cb    = (const float*)d_in[4];
    const float* gamma = (const float*)d_in[5];
    const float* beta  = (const float*)d_in[6];
    float* out = (float*)d_out;

    cudaFuncSetAttribute(k2_fused, cudaFuncAttributeMaxDynamicSharedMemorySize, SB_TOTAL);
    cudaFuncSetAttribute(k4_out,   cudaFuncAttributeMaxDynamicSharedMemorySize, K4_SMEM);

    k0_prep<<<4, 256>>>(A, edge, cw, cb);
    k2_fused<<<dim3(L_/LT_, N_), 256, SB_TOTAL>>>(x);
    k3_stats<<<1, 64>>>(gamma, beta);
    k4_out<<<dim3(L_/8, N_), 512, K4_SMEM>>>(x, out);
}

// round 13
// speedup vs baseline: 4.2617x; 1.2401x over previous
#include <cuda_runtime.h>
#include <cuda_fp16.h>
#include <cstdint>

#define N_ 4
#define CI_ 64
#define CO_ 64
#define L_ 1024
#define V_ 25
#define P_ 3
#define VP_ 32
#define KW_ 9
#define K2_ 192
#define LT_ 4

// ---------------- scratch (__device__ globals) ----------------
__device__ __align__(16) __half g_u2h[N_*L_*V_*CO_];  // [n][l][w25][c] dense pre-BN (fp16)
__device__ __align__(16) __half g_W2h[64*200];        // [c64][200]  (k=p*64+ci, pad)
__device__ __align__(16) __half g_Aeh[96*40];         // [(p,v)96][40w]
__device__ float  g_bf2[VP_*CO_];                     // [w32][c64]
__device__ float  g_sum[CO_], g_sumsq[CO_];

// ---------------- PTX primitives ----------------
__device__ __forceinline__ uint32_t smem_u32(const void* p) {
    uint32_t a;
    asm("{ .reg .u64 t; cvta.to.shared.u64 t, %1; cvt.u32.u64 %0, t; }" : "=r"(a) : "l"(p));
    return a;
}
#define LDSM4(r, addr) \
    asm volatile("ldmatrix.sync.aligned.m8n8.x4.shared.b16 {%0,%1,%2,%3}, [%4];" \
        : "=r"((r)[0]), "=r"((r)[1]), "=r"((r)[2]), "=r"((r)[3]) : "r"(addr))
#define LDSM4T(r, addr) \
    asm volatile("ldmatrix.sync.aligned.m8n8.x4.trans.shared.b16 {%0,%1,%2,%3}, [%4];" \
        : "=r"((r)[0]), "=r"((r)[1]), "=r"((r)[2]), "=r"((r)[3]) : "r"(addr))
#define MMA16816(d, a, b0, b1) \
    asm volatile("mma.sync.aligned.m16n8k16.row.col.f32.f16.f16.f32 " \
        "{%0,%1,%2,%3}, {%4,%5,%6,%7}, {%8,%9}, {%0,%1,%2,%3};" \
        : "+f"((d)[0]), "+f"((d)[1]), "+f"((d)[2]), "+f"((d)[3]) \
        : "r"((a)[0]), "r"((a)[1]), "r"((a)[2]), "r"((a)[3]), "r"(b0), "r"(b1))

// ---------------- k0: fold weights into fp16 / final layouts ----------------
__global__ void k0_prep(const float* __restrict__ A, const float* __restrict__ edge,
                        const float* __restrict__ cw, const float* __restrict__ cb) {
    int tid = threadIdx.x + blockIdx.x * blockDim.x;
    int nth = blockDim.x * gridDim.x;
    for (int i = tid; i < 64*200; i += nth) {
        int c = i / 200, k = i % 200;
        float val = 0.f;
        if (k < K2_) { int p = k >> 6, ci = k & 63; val = cw[(p*CO_ + c)*CI_ + ci]; }
        g_W2h[i] = __float2half(val);
    }
    for (int i = tid; i < 96*40; i += nth) {
        int row = i / 40, w = i % 40, p = row >> 5, v = row & 31;
        float val = 0.f;
        if (v < V_ && w < V_) { int j = (p*V_ + v)*V_ + w; val = A[j]*edge[j]; }
        g_Aeh[i] = __float2half(val);
    }
    for (int i = tid; i < VP_*CO_; i += nth) {
        int w = i >> 6, c = i & 63;
        float s = 0.f;
        if (w < V_)
            for (int p = 0; p < P_; p++) {
                float col = 0.f;
                for (int v = 0; v < V_; v++) { int j = (p*V_+v)*V_+w; col += A[j]*edge[j]; }
                s += cb[p*CO_ + c]*col;
            }
        g_bf2[i] = s;
    }
    if (tid < CO_) { g_sum[tid] = 0.f; g_sumsq[tid] = 0.f; }
}

// ---------------- k2: fused presum + double fp16 GEMM, 3 blocks/SM ----------------
#define SB_XS 0                         // half [256(lt,ci)][40v]    20480
#define SB_T  20480                     // half [192k][40w]          15360
#define SB_AE 35840                     // half [96(p,v)][40w]        7680
#define SB_U  43520                     // f32 2kh x [32w][68 c-ld]  17408
#define SB_BF 60928                     // f32 [32w][64c]             8192
#define SB_ST 69120                     // f32 stats 128               512
#define SB_TOTAL 69632                  // 68 KB -> 3 blocks/SM

__global__ void __launch_bounds__(256, 3) k2_fused(const float* __restrict__ x) {
    extern __shared__ char sm[];
    const uint32_t sbase = smem_u32(sm);
    int tid = threadIdx.x, ww = tid >> 5, lane = tid & 31;
    int n = blockIdx.y, l0 = blockIdx.x * LT_;
    const int group = lane >> 2, tq = lane & 3;

    const uint32_t ldsm40  = ((lane & 7) + ((lane >> 3) & 1) * 8) * 80
                           + ((lane >> 4) & 1) * 16;
    const uint32_t ldsm200 = ((lane & 7) + ((lane >> 3) & 1) * 8) * 400
                           + ((lane >> 4) & 1) * 16;

    // ---- phase 0: stage W2 transiently; load BF; zero stats ----
    {
        const float4* wsrc = (const float4*)g_W2h;
        float4* wdst = (float4*)sm;
        for (int i = tid; i < 3200; i += 256) wdst[i] = wsrc[i];
        const float4* bsrc = (const float4*)g_bf2;
        float4* bdst = (float4*)(sm + SB_BF);
        for (int i = tid; i < 512; i += 256) bdst[i] = bsrc[i];
        float* st = (float*)(sm + SB_ST);
        if (tid < 128) st[tid] = 0.f;
    }
    __syncthreads();

    // ---- phase 1: cache this warp's stage-2 A fragments (24 regs) ----
    const int r_s2 = ww & 3;
    const int kh   = ww >> 2;
    uint32_t wf[6][4];
    #pragma unroll
    for (int i = 0; i < 6; i++)
        LDSM4(wf[i], sbase + (uint32_t)((r_s2*16)*200 + (kh*6 + i)*16)*2 + ldsm200);
    __syncthreads();

    // ---- phase 2: AE copy + fused temporal presum -> XS (half) ----
    {
        const float4* asrc = (const float4*)g_Aeh;
        float4* adst = (float4*)(sm + SB_AE);
        for (int i = tid; i < 480; i += 256) adst[i] = asrc[i];
    }
    __half* xs = (__half*)(sm + SB_XS);
    for (int it = 0; it < 8; it++) {
        int pair = tid + it*256;
        int ci = pair >> 5, v = pair & 31;
        if (v >= V_) {
            #pragma unroll
            for (int j = 0; j < LT_; j++) xs[(j*64 + ci)*40 + v] = __float2half(0.f);
            continue;
        }
        const float* xb = x + ((size_t)(n*CI_ + ci)*L_)*V_ + v;
        float vals[KW_ - 1 + LT_];
        #pragma unroll
        for (int i = 0; i < KW_ - 1 + LT_; i++) {
            int l = l0 - (KW_ - 1) + i;
            vals[i] = (l >= 0) ? xb[(size_t)l*V_] : 0.f;
        }
        float s = 0.f;
        #pragma unroll
        for (int i = 0; i < KW_ - 1; i++) s += vals[i];
        #pragma unroll
        for (int j = 0; j < LT_; j++) {
            s += vals[j + KW_ - 1];
            xs[(j*64 + ci)*40 + v] = __float2half(s);
            s -= vals[j];
        }
    }
    __syncthreads();

    const int myc = tid & 63;
    float csum = 0.f, csum2 = 0.f;
    float* Uf = (float*)(sm + SB_U);
    const float* BF = (const float*)(sm + SB_BF);

    for (int lt = 0; lt < LT_; lt++) {
        // ---- stage 1 ----
        {
            int ct = ww & 3, h = ww >> 2;
            uint32_t a[2][4];
            #pragma unroll
            for (int ks = 0; ks < 2; ks++)
                LDSM4(a[ks], sbase + SB_XS
                      + (uint32_t)((lt*64 + ct*16)*40 + ks*16)*2 + ldsm40);
            #pragma unroll
            for (int q = 0; q < 3; q++) {
                int idx = h*3 + q, p = idx >> 1, wt = idx & 1;
                float d[2][4] = {{0.f,0.f,0.f,0.f},{0.f,0.f,0.f,0.f}};
                #pragma unroll
                for (int ks = 0; ks < 2; ks++) {
                    uint32_t b[4];
                    LDSM4T(b, sbase + SB_AE
                           + (uint32_t)((p*32 + ks*16)*40 + wt*16)*2 + ldsm40);
                    MMA16816(d[0], a[ks], b[0], b[1]);
                    MMA16816(d[1], a[ks], b[2], b[3]);
                }
                #pragma unroll
                for (int j = 0; j < 2; j++) {
                    int wcol = wt*16 + j*8 + tq*2;
                    int row  = p*64 + ct*16 + group;
                    *(__half2*)(sm + SB_T + (row*40 + wcol)*2)
                        = __floats2half2_rn(d[j][0], d[j][1]);
                    *(__half2*)(sm + SB_T + ((row + 8)*40 + wcol)*2)
                        = __floats2half2_rn(d[j][2], d[j][3]);
                }
            }
        }
        __syncthreads();

        // ---- stage 2 ----
        {
            float e[4][4] = {{0.f,0.f,0.f,0.f},{0.f,0.f,0.f,0.f},
                             {0.f,0.f,0.f,0.f},{0.f,0.f,0.f,0.f}};
            #pragma unroll
            for (int i = 0; i < 6; i++) {
                uint32_t b0[4], b1[4];
                uint32_t tb = sbase + SB_T + (uint32_t)(((kh*6 + i)*16)*40)*2 + ldsm40;
                LDSM4T(b0, tb);
                LDSM4T(b1, tb + 32);
                MMA16816(e[0], wf[i], b0[0], b0[1]);
                MMA16816(e[1], wf[i], b0[2], b0[3]);
                MMA16816(e[2], wf[i], b1[0], b1[1]);
                MMA16816(e[3], wf[i], b1[2], b1[3]);
            }
            float* U = Uf + kh*2176;
            #pragma unroll
            for (int j = 0; j < 4; j++) {
                int w0 = j*8 + tq*2;
                int c0 = r_s2*16 + group;
                U[w0*68 + c0]           = e[j][0];
                U[(w0 + 1)*68 + c0]     = e[j][1];
                U[w0*68 + c0 + 8]       = e[j][2];
                U[(w0 + 1)*68 + c0 + 8] = e[j][3];
            }
        }
        __syncthreads();

        // ---- epilogue: sum K halves + bias*cnt + stats + store fp16 u2 ----
        {
            int l = l0 + lt;
            float cnt = (float)((l + 1 < KW_) ? (l + 1) : KW_);
            __half* ug = g_u2h + (size_t)(n*L_ + l)*(V_*CO_);
            for (int j = tid; j < V_*CO_; j += 256) {
                int w = j >> 6, c = j & 63;          // c == myc
                float val = Uf[w*68 + c] + Uf[2176 + w*68 + c] + cnt*BF[w*64 + c];
                csum  += val;
                csum2 += val*val;
                ug[j] = __float2half(val);
            }
        }
    }

    float* st = (float*)(sm + SB_ST);
    atomicAdd(&st[myc], csum);
    atomicAdd(&st[64 + myc], csum2);
    __syncthreads();
    if (tid < CO_) {
        atomicAdd(&g_sum[tid],   st[tid]);
        atomicAdd(&g_sumsq[tid], st[64 + tid]);
    }
}

// ---------------- k4: stats finalize + transpose + BN + relu + residual + relu ----
#define K4_SMEM (200*65*4)
__global__ void __launch_bounds__(512) k4_out(const float* __restrict__ x,
                                              const float* __restrict__ gamma,
                                              const float* __restrict__ beta,
                                              float* __restrict__ out) {
    extern __shared__ float sm4[];
    __shared__ float s_sc[64], s_sh[64];
    int tid = threadIdx.x;
    int n = blockIdx.y, l0 = blockIdx.x * 8;

    // prologue: finalize BN stats locally (replaces k3 launch)
    if (tid < CO_) {
        const float cnt = (float)(N_*L_*V_);
        float mean = g_sum[tid] / cnt;
        float var  = g_sumsq[tid] / cnt - mean*mean;
        float inv  = rsqrtf(var + 1e-5f);
        float sc   = gamma[tid]*inv;
        s_sc[tid] = sc;
        s_sh[tid] = beta[tid] - mean*sc;
    }

    // load fp16 u2 tile -> fp32 smem [200 rows (l,w)][ld 65]
    {
        const __half2* src = (const __half2*)(g_u2h + (size_t)(n*L_ + l0)*(V_*CO_));
        for (int i = tid; i < 8*V_*CO_/2; i += 512) {
            float2 uv = __half22float2(src[i]);
            int rr = i >> 5, c = (i & 31)*2;
            sm4[rr*65 + c]     = uv.x;
            sm4[rr*65 + c + 1] = uv.y;
        }
    }
    __syncthreads();

    // store phase: fixed channel per thread, fully unrolled for MLP
    {
        int c = tid >> 3, rg = tid & 7;
        float sc = s_sc[c], sh = s_sh[c];
        const float* xc = x   + ((size_t)(n*CO_ + c)*L_ + l0)*V_;
        float*       oc = out + ((size_t)(n*CO_ + c)*L_ + l0)*V_;
        float xv[V_];
        #pragma unroll
        for (int i = 0; i < V_; i++) xv[i] = xc[i*8 + rg];
        #pragma unroll
        for (int i = 0; i < V_; i++) {
            int rr = i*8 + rg;
            float val = sm4[rr*65 + c]*sc + sh;
            oc[rr] = fmaxf(fmaxf(val, 0.f) + xv[i], 0.f);
        }
    }
}

// ---------------- launch ----------------
extern "C" void kernel_launch(void* const* d_in, const int* in_sizes, int n_in,
                              void* d_out, int out_size) {
    const float* x     = (const float*)d_in[0];
    const float* A     = (const float*)d_in[1];
    const float* edge  = (const float*)d_in[2];
    const float* cw    = (const float*)d_in[3];
    const float* cb    = (const float*)d_in[4];
    const float* gamma = (const float*)d_in[5];
    const float* beta  = (const float*)d_in[6];
    float* out = (float*)d_out;

    cudaFuncSetAttribute(k2_fused, cudaFuncAttributeMaxDynamicSharedMemorySize, SB_TOTAL);
    cudaFuncSetAttribute(k4_out,   cudaFuncAttributeMaxDynamicSharedMemorySize, K4_SMEM);

    k0_prep<<<4, 256>>>(A, edge, cw, cb);
    k2_fused<<<dim3(L_/LT_, N_), 256, SB_TOTAL>>>(x);
    k4_out<<<dim3(L_/8, N_), 512, K4_SMEM>>>(x, gamma, beta, out);
}